// round 2
// baseline (speedup 1.0000x reference)
#include <cuda_runtime.h>

#define BB  32
#define DD  128
#define CLN 1024
#define QLN 512
#define NS  8   // column-reduction split factor

// ---------------- scratch (device globals; no allocations allowed) ----------
// g_Aeff is consumed by gemm1 and then dead -> reused as the output buffer A.
__device__ float g_Ct[BB * CLN * DD];          // C transposed: (B, CL, D)
__device__ float g_Qt[BB * QLN * DD];          // Q transposed: (B, QL, D)
__device__ float g_Aeff[BB * CLN * DD];        // wq + wqc*Ct, later A = S1 @ Qt
__device__ float g_bias[BB * CLN];             // sum_d wc*Ct
__device__ float g_S[(size_t)BB * CLN * QLN];  // similarity matrix (64 MiB)
__device__ float g_rmax[BB * CLN];             // row softmax stats (over q)
__device__ float g_rinv[BB * CLN];
__device__ float g_cmax[BB * QLN];             // col softmax stats (over c)
__device__ float g_cinv[BB * QLN];
__device__ float g_cpm[NS * BB * QLN];         // col partials
__device__ float g_cps[NS * BB * QLN];
__device__ float g_T[BB * QLN * DD];           // S2tC
__device__ float g_Bm[BB * CLN * DD];          // Bm = S1 @ S2tC

// ---------------- transposes: (B, R, L) -> (B, L, R) -------------------------
__global__ __launch_bounds__(256) void tr_C_kernel(const float* __restrict__ in) {
    __shared__ float t[32][33];
    const int R = DD, L = CLN;
    int b = blockIdx.z;
    int l0 = blockIdx.x << 5, r0 = blockIdx.y << 5;
    int tx = threadIdx.x, ty = threadIdx.y;
    const float* ip = in + (size_t)b * R * L;
    float* op = g_Ct + (size_t)b * R * L;
#pragma unroll
    for (int i = 0; i < 32; i += 8) t[ty + i][tx] = ip[(size_t)(r0 + ty + i) * L + l0 + tx];
    __syncthreads();
#pragma unroll
    for (int i = 0; i < 32; i += 8) op[(size_t)(l0 + ty + i) * R + r0 + tx] = t[tx][ty + i];
}

__global__ __launch_bounds__(256) void tr_Q_kernel(const float* __restrict__ in) {
    __shared__ float t[32][33];
    const int R = DD, L = QLN;
    int b = blockIdx.z;
    int l0 = blockIdx.x << 5, r0 = blockIdx.y << 5;
    int tx = threadIdx.x, ty = threadIdx.y;
    const float* ip = in + (size_t)b * R * L;
    float* op = g_Qt + (size_t)b * R * L;
#pragma unroll
    for (int i = 0; i < 32; i += 8) t[ty + i][tx] = ip[(size_t)(r0 + ty + i) * L + l0 + tx];
    __syncthreads();
#pragma unroll
    for (int i = 0; i < 32; i += 8) op[(size_t)(l0 + ty + i) * R + r0 + tx] = t[tx][ty + i];
}

// ---------------- prep: Aeff = wq + wqc*Ct ; bias = sum_d wc*Ct ---------------
__global__ __launch_bounds__(128) void prep_kernel(const float* __restrict__ W) {
    int b = blockIdx.y, c = blockIdx.x, d = threadIdx.x;
    size_t rc = (size_t)b * CLN + c;
    const float* w = W + rc * (3 * DD);
    float ct = g_Ct[(rc << 7) + d];
    g_Aeff[(rc << 7) + d] = w[d] + w[2 * DD + d] * ct;
    float v = w[DD + d] * ct;
#pragma unroll
    for (int o = 16; o; o >>= 1) v += __shfl_xor_sync(0xffffffffu, v, o);
    __shared__ float red[4];
    if ((d & 31) == 0) red[d >> 5] = v;
    __syncthreads();
    if (d == 0) g_bias[rc] = red[0] + red[1] + red[2] + red[3];
}

// ---------------- GEMM1: S = Aeff @ Qt^T + bias  (M=CL,N=QL,K=D) --------------
// BM=128, BN=64, BK=16, 256 threads, micro-tile 8x4
__global__ __launch_bounds__(256) void gemm1_kernel() {
    int b = blockIdx.z;
    int n0 = blockIdx.x << 6;
    int m0 = blockIdx.y << 7;
    const float* Ap = g_Aeff + (size_t)b * CLN * DD;
    const float* Bp = g_Qt + (size_t)b * QLN * DD;
    __shared__ float As[16][128];
    __shared__ float Bs[16][64];
    int t = threadIdx.x;
    int arow = t >> 1, akc = (t & 1) << 3;
    int brow = t >> 2, bkc = (t & 3) << 2;
    int tx = t & 15, ty = t >> 4;
    float acc[8][4] = {};
    for (int k0 = 0; k0 < DD; k0 += 16) {
        const float* ap = Ap + (size_t)(m0 + arow) * DD + k0 + akc;
        float4 a0 = *(const float4*)ap;
        float4 a1 = *(const float4*)(ap + 4);
        As[akc + 0][arow] = a0.x; As[akc + 1][arow] = a0.y;
        As[akc + 2][arow] = a0.z; As[akc + 3][arow] = a0.w;
        As[akc + 4][arow] = a1.x; As[akc + 5][arow] = a1.y;
        As[akc + 6][arow] = a1.z; As[akc + 7][arow] = a1.w;
        float4 bv = *(const float4*)(Bp + (size_t)(n0 + brow) * DD + k0 + bkc);
        Bs[bkc + 0][brow] = bv.x; Bs[bkc + 1][brow] = bv.y;
        Bs[bkc + 2][brow] = bv.z; Bs[bkc + 3][brow] = bv.w;
        __syncthreads();
#pragma unroll
        for (int k = 0; k < 16; ++k) {
            float4 a4 = *(const float4*)&As[k][ty << 3];
            float4 a5 = *(const float4*)&As[k][(ty << 3) + 4];
            float4 b4 = *(const float4*)&Bs[k][tx << 2];
            float am[8] = {a4.x, a4.y, a4.z, a4.w, a5.x, a5.y, a5.z, a5.w};
            float bn[4] = {b4.x, b4.y, b4.z, b4.w};
#pragma unroll
            for (int i = 0; i < 8; ++i)
#pragma unroll
                for (int j = 0; j < 4; ++j) acc[i][j] += am[i] * bn[j];
        }
        __syncthreads();
    }
#pragma unroll
    for (int i = 0; i < 8; ++i) {
        int row = m0 + (ty << 3) + i;
        float bb = g_bias[b * CLN + row];
        float4 v = make_float4(acc[i][0] + bb, acc[i][1] + bb, acc[i][2] + bb, acc[i][3] + bb);
        *(float4*)(g_S + ((size_t)b * CLN + row) * QLN + n0 + (tx << 2)) = v;
    }
}

// ---------------- row softmax stats (over q), warp per row --------------------
__global__ __launch_bounds__(256) void rowred_kernel() {
    int row = blockIdx.x * 8 + (threadIdx.x >> 5);
    int lane = threadIdx.x & 31;
    const float* p = g_S + (size_t)row * QLN;
    float m = -1e30f;
    for (int q = lane; q < QLN; q += 32) m = fmaxf(m, p[q]);
#pragma unroll
    for (int o = 16; o; o >>= 1) m = fmaxf(m, __shfl_xor_sync(0xffffffffu, m, o));
    float s = 0.f;
    for (int q = lane; q < QLN; q += 32) s += __expf(p[q] - m);
#pragma unroll
    for (int o = 16; o; o >>= 1) s += __shfl_xor_sync(0xffffffffu, s, o);
    if (lane == 0) { g_rmax[row] = m; g_rinv[row] = 1.f / s; }
}

// ---------------- col softmax stats (over c), split into NS chunks ------------
__global__ __launch_bounds__(128) void colred_kernel() {
    int q = blockIdx.x * 128 + threadIdx.x;
    int b = blockIdx.y, s = blockIdx.z;
    const float* p = g_S + ((size_t)b * CLN + (size_t)s * (CLN / NS)) * QLN + q;
    float m = -1e30f;
#pragma unroll 4
    for (int c = 0; c < CLN / NS; ++c) m = fmaxf(m, p[(size_t)c * QLN]);
    float sum = 0.f;
#pragma unroll 4
    for (int c = 0; c < CLN / NS; ++c) sum += __expf(p[(size_t)c * QLN] - m);
    g_cpm[((size_t)s * BB + b) * QLN + q] = m;
    g_cps[((size_t)s * BB + b) * QLN + q] = sum;
}

__global__ __launch_bounds__(128) void colcomb_kernel() {
    int q = blockIdx.x * 128 + threadIdx.x;
    int b = blockIdx.y;
    float M = -1e30f;
#pragma unroll
    for (int s = 0; s < NS; ++s) M = fmaxf(M, g_cpm[((size_t)s * BB + b) * QLN + q]);
    float S = 0.f;
#pragma unroll
    for (int s = 0; s < NS; ++s)
        S += g_cps[((size_t)s * BB + b) * QLN + q] * __expf(g_cpm[((size_t)s * BB + b) * QLN + q] - M);
    g_cmax[b * QLN + q] = M;
    g_cinv[b * QLN + q] = 1.f / S;
}

// ---------------- GEMM2/4: Cout = diag(rinv) * exp(S - rmax) @ Bmat -----------
// M=CL, N=D=128, K=QL ; BM=64, BN=128, BK=16, 256 threads, micro-tile 4x8
// which=0: Bmat=Qt -> g_Aeff (reused as A) ; which=1: Bmat=g_T -> g_Bm
__global__ __launch_bounds__(256) void gemmA_kernel(int which) {
    int b = blockIdx.z;
    int m0 = blockIdx.y << 6;
    const float* Sp = g_S + (size_t)b * CLN * QLN;
    const float* Bp = (which ? g_T : g_Qt) + (size_t)b * QLN * DD;
    float* Co = (which ? g_Bm : g_Aeff) + (size_t)b * CLN * DD;
    __shared__ float As[16][64];
    __shared__ float Bs[16][128];
    int t = threadIdx.x;
    int arow = t >> 2, akc = (t & 3) << 2;
    int bkr = t >> 4, bnc = (t & 15) << 3;
    int tx = t & 15, ty = t >> 4;
    float rm = g_rmax[b * CLN + m0 + arow];
    float acc[4][8] = {};
    for (int k0 = 0; k0 < QLN; k0 += 16) {
        float4 av = *(const float4*)(Sp + (size_t)(m0 + arow) * QLN + k0 + akc);
        As[akc + 0][arow] = __expf(av.x - rm);
        As[akc + 1][arow] = __expf(av.y - rm);
        As[akc + 2][arow] = __expf(av.z - rm);
        As[akc + 3][arow] = __expf(av.w - rm);
        const float* bp = Bp + (size_t)(k0 + bkr) * DD + bnc;
        *(float4*)&Bs[bkr][bnc] = *(const float4*)bp;
        *(float4*)&Bs[bkr][bnc + 4] = *(const float4*)(bp + 4);
        __syncthreads();
#pragma unroll
        for (int k = 0; k < 16; ++k) {
            float4 a4 = *(const float4*)&As[k][ty << 2];
            float4 b4 = *(const float4*)&Bs[k][tx << 3];
            float4 b5 = *(const float4*)&Bs[k][(tx << 3) + 4];
            float am[4] = {a4.x, a4.y, a4.z, a4.w};
            float bn[8] = {b4.x, b4.y, b4.z, b4.w, b5.x, b5.y, b5.z, b5.w};
#pragma unroll
            for (int i = 0; i < 4; ++i)
#pragma unroll
                for (int j = 0; j < 8; ++j) acc[i][j] += am[i] * bn[j];
        }
        __syncthreads();
    }
#pragma unroll
    for (int i = 0; i < 4; ++i) {
        int row = m0 + (ty << 2) + i;
        float sc = g_rinv[b * CLN + row];
        float* o = Co + (size_t)row * DD + (tx << 3);
        *(float4*)o = make_float4(acc[i][0] * sc, acc[i][1] * sc, acc[i][2] * sc, acc[i][3] * sc);
        *(float4*)(o + 4) = make_float4(acc[i][4] * sc, acc[i][5] * sc, acc[i][6] * sc, acc[i][7] * sc);
    }
}

// ---------------- GEMM3: S2tC = diag(cinv) * exp(S - cmax)^T @ Ct -------------
// M=QL, N=D=128, K=CL ; BM=64, BN=128, BK=16 (A loaded transposed from S)
__global__ __launch_bounds__(256) void gemm3_kernel() {
    int b = blockIdx.z;
    int m0 = blockIdx.y << 6;  // q0
    const float* Sp = g_S + (size_t)b * CLN * QLN;
    const float* Bp = g_Ct + (size_t)b * CLN * DD;
    __shared__ float As[16][64];
    __shared__ float Bs[16][128];
    __shared__ float cms[64], cis[64];
    int t = threadIdx.x;
    if (t < 64) {
        cms[t] = g_cmax[b * QLN + m0 + t];
        cis[t] = g_cinv[b * QLN + m0 + t];
    }
    __syncthreads();
    int acr = t >> 4, aqc = (t & 15) << 2;
    int bkr = t >> 4, bnc = (t & 15) << 3;
    int tx = t & 15, ty = t >> 4;
    float acc[4][8] = {};
    for (int k0 = 0; k0 < CLN; k0 += 16) {
        float4 av = *(const float4*)(Sp + (size_t)(k0 + acr) * QLN + m0 + aqc);
        As[acr][aqc + 0] = __expf(av.x - cms[aqc + 0]);
        As[acr][aqc + 1] = __expf(av.y - cms[aqc + 1]);
        As[acr][aqc + 2] = __expf(av.z - cms[aqc + 2]);
        As[acr][aqc + 3] = __expf(av.w - cms[aqc + 3]);
        const float* bp = Bp + (size_t)(k0 + bkr) * DD + bnc;
        *(float4*)&Bs[bkr][bnc] = *(const float4*)bp;
        *(float4*)&Bs[bkr][bnc + 4] = *(const float4*)(bp + 4);
        __syncthreads();
#pragma unroll
        for (int k = 0; k < 16; ++k) {
            float4 a4 = *(const float4*)&As[k][ty << 2];
            float4 b4 = *(const float4*)&Bs[k][tx << 3];
            float4 b5 = *(const float4*)&Bs[k][(tx << 3) + 4];
            float am[4] = {a4.x, a4.y, a4.z, a4.w};
            float bn[8] = {b4.x, b4.y, b4.z, b4.w, b5.x, b5.y, b5.z, b5.w};
#pragma unroll
            for (int i = 0; i < 4; ++i)
#pragma unroll
                for (int j = 0; j < 8; ++j) acc[i][j] += am[i] * bn[j];
        }
        __syncthreads();
    }
#pragma unroll
    for (int i = 0; i < 4; ++i) {
        int q = m0 + (ty << 2) + i;
        float sc = cis[(ty << 2) + i];
        float* o = g_T + ((size_t)b * QLN + q) * DD + (tx << 3);
        *(float4*)o = make_float4(acc[i][0] * sc, acc[i][1] * sc, acc[i][2] * sc, acc[i][3] * sc);
        *(float4*)(o + 4) = make_float4(acc[i][4] * sc, acc[i][5] * sc, acc[i][6] * sc, acc[i][7] * sc);
    }
}

// ---------------- output assembly: out (B, 4D, CL) ----------------------------
__global__ __launch_bounds__(256) void final_kernel(const float* __restrict__ C,
                                                    float* __restrict__ out) {
    __shared__ float tA[32][33], tB[32][33];
    int b = blockIdx.z;
    int c0 = blockIdx.x << 5, d0 = blockIdx.y << 5;
    int tx = threadIdx.x, ty = threadIdx.y;
    const float* Ap = g_Aeff + (size_t)b * CLN * DD;   // holds A = S1 @ Qt
    const float* Bp = g_Bm + (size_t)b * CLN * DD;
#pragma unroll
    for (int i = 0; i < 32; i += 8) {
        tA[ty + i][tx] = Ap[(size_t)(c0 + ty + i) * DD + d0 + tx];
        tB[ty + i][tx] = Bp[(size_t)(c0 + ty + i) * DD + d0 + tx];
    }
    __syncthreads();
    size_t ob = (size_t)b * (4 * DD) * CLN;
#pragma unroll
    for (int i = 0; i < 32; i += 8) {
        int d = d0 + ty + i, c = c0 + tx;
        float cv = C[((size_t)b * DD + d) * CLN + c];
        float av = tA[tx][ty + i];
        float bm = tB[tx][ty + i];
        out[ob + (size_t)d * CLN + c] = cv;
        out[ob + (size_t)(DD + d) * CLN + c] = av;
        out[ob + (size_t)(2 * DD + d) * CLN + c] = cv * av;
        out[ob + (size_t)(3 * DD + d) * CLN + c] = cv * bm;
    }
}

// ---------------- launch ------------------------------------------------------
extern "C" void kernel_launch(void* const* d_in, const int* in_sizes, int n_in,
                              void* d_out, int out_size) {
    const float* C = (const float*)d_in[0];
    const float* Q = (const float*)d_in[1];
    const float* W = (const float*)d_in[2];
    float* out = (float*)d_out;

    tr_C_kernel<<<dim3(CLN / 32, DD / 32, BB), dim3(32, 8)>>>(C);
    tr_Q_kernel<<<dim3(QLN / 32, DD / 32, BB), dim3(32, 8)>>>(Q);
    prep_kernel<<<dim3(CLN, BB), 128>>>(W);
    gemm1_kernel<<<dim3(QLN / 64, CLN / 128, BB), 256>>>();
    rowred_kernel<<<BB * CLN / 8, 256>>>();
    colred_kernel<<<dim3(QLN / 128, BB, NS), 128>>>();
    colcomb_kernel<<<dim3(QLN / 128, BB), 128>>>();
    gemmA_kernel<<<dim3(1, CLN / 64, BB), 256>>>(0);  // A = S1 @ Qt
    gemm3_kernel<<<dim3(1, QLN / 64, BB), 256>>>();   // S2tC = S2^T @ Ct
    gemmA_kernel<<<dim3(1, CLN / 64, BB), 256>>>(1);  // Bm = S1 @ S2tC
    final_kernel<<<dim3(CLN / 32, DD / 32, BB), dim3(32, 8)>>>(C, out);
}

// round 3
// speedup vs baseline: 2.6251x; 2.6251x over previous
#include <cuda_runtime.h>

#define BB  32
#define DD  128
#define CLN 1024
#define QLN 512

// ---------------- scratch (device globals; no allocations allowed) ----------
__device__ float g_Ct[BB * CLN * DD];           // C^T (B, CL, D) - for prep only
__device__ float g_Qt[BB * QLN * DD];           // Q^T (B, QL, D) - G1 B operand
__device__ float g_Aeff[BB * CLN * DD];         // wq + wqc*Ct ; later reused as A
__device__ float g_bias[BB * CLN];              // sum_d wc*Ct
__device__ float g_S[(size_t)BB * CLN * QLN];   // S   (B, CL, QL)
__device__ float g_St[(size_t)BB * QLN * CLN];  // S^T (B, QL, CL)
__device__ float g_rmax[BB * CLN];
__device__ float g_rinv[BB * CLN];
__device__ float g_cmax[BB * QLN];
__device__ float g_cinv[BB * QLN];
__device__ float g_T[BB * QLN * DD];            // S2tC (B, QL, D)
__device__ float g_Tt[BB * DD * QLN];           // S2tC^T (B, D, QL)
__device__ float g_Bm[BB * CLN * DD];           // Bm

// ---------------- generic transpose: in (B,R,L) -> out (B,L,R) ---------------
__global__ __launch_bounds__(256) void tr_kernel(const float* __restrict__ in,
                                                 float* __restrict__ out,
                                                 int R, int L) {
    __shared__ float t[32][33];
    int b = blockIdx.z;
    int l0 = blockIdx.x << 5, r0 = blockIdx.y << 5;
    int tx = threadIdx.x, ty = threadIdx.y;
    const float* ip = in + (size_t)b * R * L;
    float* op = out + (size_t)b * R * L;
#pragma unroll
    for (int i = 0; i < 32; i += 8) t[ty + i][tx] = ip[(size_t)(r0 + ty + i) * L + l0 + tx];
    __syncthreads();
#pragma unroll
    for (int i = 0; i < 32; i += 8) op[(size_t)(l0 + ty + i) * R + r0 + tx] = t[tx][ty + i];
}

// ---------------- prep: Aeff = wq + wqc*Ct ; bias = sum_d wc*Ct ---------------
__global__ __launch_bounds__(128) void prep_kernel(const float* __restrict__ W) {
    int b = blockIdx.y, c = blockIdx.x, d = threadIdx.x;
    size_t rc = (size_t)b * CLN + c;
    const float* w = W + rc * (3 * DD);
    float ct = g_Ct[(rc << 7) + d];
    g_Aeff[(rc << 7) + d] = w[d] + w[2 * DD + d] * ct;
    float v = w[DD + d] * ct;
#pragma unroll
    for (int o = 16; o; o >>= 1) v += __shfl_xor_sync(0xffffffffu, v, o);
    __shared__ float red[4];
    if ((d & 31) == 0) red[d >> 5] = v;
    __syncthreads();
    if (d == 0) g_bias[rc] = red[0] + red[1] + red[2] + red[3];
}

// ---------------- mma.sync tf32 helper ----------------------------------------
#define MMA_TF32(D, A, B)                                                          \
    asm volatile(                                                                  \
        "mma.sync.aligned.m16n8k8.row.col.f32.tf32.tf32.f32 "                      \
        "{%0,%1,%2,%3}, {%4,%5,%6,%7}, {%8,%9}, {%0,%1,%2,%3};"                    \
        : "+f"((D)[0]), "+f"((D)[1]), "+f"((D)[2]), "+f"((D)[3])                   \
        : "r"((A)[0]), "r"((A)[1]), "r"((A)[2]), "r"((A)[3]),                      \
          "r"((B)[0]), "r"((B)[1]))

// BM=128, BN=128, BK=16, 256 threads (8 warps: 2x4), warp tile 64x32.
// smem: double-buffered As/Bs, row-major [row][k] with stride 20 (conflict-free).

// ---------------- GEMM1: S = Aeff @ Qt^T + bias ; also writes S^T -------------
__global__ __launch_bounds__(256) void gemm1_kernel() {
    int b = blockIdx.z;
    int n0 = blockIdx.x << 7;
    int m0 = blockIdx.y << 7;
    const float* Ap = g_Aeff + (size_t)b * CLN * DD;
    const float* Bp = g_Qt + (size_t)b * QLN * DD;
    __shared__ float sh[10240];
    int t = threadIdx.x, lane = t & 31, warp = t >> 5;
    int g = lane >> 2, tg = lane & 3;
    int wm = (warp >> 2) << 6, wn = (warp & 3) << 5;
    int arow = t >> 1, ak = (t & 1) << 3;
    const float* Ag = Ap + (size_t)(m0 + arow) * DD + ak;
    const float* Bg = Bp + (size_t)(n0 + arow) * DD + ak;
    float acc[4][4][4] = {};
    const int KT = DD / 16;
    float4 pa0 = *(const float4*)Ag, pa1 = *(const float4*)(Ag + 4);
    float4 pb0 = *(const float4*)Bg, pb1 = *(const float4*)(Bg + 4);
    {
        float* as = sh + arow * 20 + ak;
        *(float4*)as = pa0; *(float4*)(as + 4) = pa1;
        float* bs = sh + 5120 + arow * 20 + ak;
        *(float4*)bs = pb0; *(float4*)(bs + 4) = pb1;
    }
    __syncthreads();
    for (int ks = 0; ks < KT; ++ks) {
        if (ks + 1 < KT) {
            const float* ag = Ag + (ks + 1) * 16;
            pa0 = *(const float4*)ag; pa1 = *(const float4*)(ag + 4);
            const float* bg = Bg + (ks + 1) * 16;
            pb0 = *(const float4*)bg; pb1 = *(const float4*)(bg + 4);
        }
        const float* As = sh + (ks & 1) * 2560;
        const float* Bs = sh + 5120 + (ks & 1) * 2560;
#pragma unroll
        for (int kk = 0; kk < 2; ++kk) {
            int kc = (kk << 3) + tg;
            unsigned a[4][4], bf[4][2];
#pragma unroll
            for (int mi = 0; mi < 4; ++mi) {
                const float* p = As + (wm + (mi << 4) + g) * 20 + kc;
                a[mi][0] = __float_as_uint(p[0]);
                a[mi][1] = __float_as_uint(p[160]);
                a[mi][2] = __float_as_uint(p[4]);
                a[mi][3] = __float_as_uint(p[164]);
            }
#pragma unroll
            for (int ni = 0; ni < 4; ++ni) {
                const float* p = Bs + (wn + (ni << 3) + g) * 20 + kc;
                bf[ni][0] = __float_as_uint(p[0]);
                bf[ni][1] = __float_as_uint(p[4]);
            }
#pragma unroll
            for (int mi = 0; mi < 4; ++mi)
#pragma unroll
                for (int ni = 0; ni < 4; ++ni) MMA_TF32(acc[mi][ni], a[mi], bf[ni]);
        }
        if (ks + 1 < KT) {
            float* as = sh + ((ks + 1) & 1) * 2560 + arow * 20 + ak;
            *(float4*)as = pa0; *(float4*)(as + 4) = pa1;
            float* bs = sh + 5120 + ((ks + 1) & 1) * 2560 + arow * 20 + ak;
            *(float4*)bs = pb0; *(float4*)(bs + 4) = pb1;
            __syncthreads();
        }
    }
    // epilogue: add bias, write S
    float* Sp = g_S + (size_t)b * CLN * QLN;
    float* Stp = g_St + (size_t)b * QLN * CLN;
    const float* bp = g_bias + b * CLN;
#pragma unroll
    for (int mi = 0; mi < 4; ++mi)
#pragma unroll
        for (int h = 0; h < 2; ++h) {
            int row = m0 + wm + (mi << 4) + g + (h << 3);
            float bbv = bp[row];
#pragma unroll
            for (int ni = 0; ni < 4; ++ni) {
                int col = n0 + wn + (ni << 3) + (tg << 1);
                float2 v = make_float2(acc[mi][ni][2 * h] + bbv, acc[mi][ni][2 * h + 1] + bbv);
                *(float2*)(Sp + (size_t)row * QLN + col) = v;
            }
        }
    // write S^T via smem staging (4 chunks of 32 m-rows)
    for (int ch = 0; ch < 4; ++ch) {
        __syncthreads();
        if ((ch >> 1) == (warp >> 2)) {
            int mi0 = (ch & 1) << 1;
#pragma unroll
            for (int mm = 0; mm < 2; ++mm) {
                int mi = mi0 + mm;
#pragma unroll
                for (int h = 0; h < 2; ++h) {
                    int ml = (mm << 4) + g + (h << 3);
                    int row = m0 + wm + (mi << 4) + g + (h << 3);
                    float bbv = bp[row];
#pragma unroll
                    for (int ni = 0; ni < 4; ++ni) {
                        int n = wn + (ni << 3) + (tg << 1);
                        sh[ml * 133 + n] = acc[mi][ni][2 * h] + bbv;
                        sh[ml * 133 + n + 1] = acc[mi][ni][2 * h + 1] + bbv;
                    }
                }
            }
        }
        __syncthreads();
        int cl = t & 31;
        int qw = t >> 5;
#pragma unroll
        for (int i = 0; i < 16; ++i) {
            int qq = qw + (i << 3);
            Stp[(size_t)(n0 + qq) * CLN + m0 + (ch << 5) + cl] = sh[cl * 133 + qq];
        }
    }
}

// ---------------- generic exp-GEMM: Co = diag(inv) * exp(A - max) @ B^T -------
// A: (M rows, K cols, lda) ; B: (N=128 rows, K cols, ldb) ; Co: (M, 128, ldc)
__global__ __launch_bounds__(256) void gemm_exp_kernel(
    const float* __restrict__ A, int lda, size_t aB,
    const float* __restrict__ smax, const float* __restrict__ sinv, int sstr,
    const float* __restrict__ Bmat, int ldb, size_t bB,
    float* __restrict__ Co, int ldc, size_t cB, int K) {
    int b = blockIdx.z;
    int n0 = blockIdx.x << 7;
    int m0 = blockIdx.y << 7;
    const float* Ap = A + (size_t)b * aB;
    const float* Bp = Bmat + (size_t)b * bB;
    __shared__ float sh[10240];
    int t = threadIdx.x, lane = t & 31, warp = t >> 5;
    int g = lane >> 2, tg = lane & 3;
    int wm = (warp >> 2) << 6, wn = (warp & 3) << 5;
    int arow = t >> 1, ak = (t & 1) << 3;
    const float* Ag = Ap + (size_t)(m0 + arow) * lda + ak;
    const float* Bg = Bp + (size_t)(n0 + arow) * ldb + ak;
    float rm = smax[b * sstr + m0 + arow];
    float acc[4][4][4] = {};
    const int KT = K / 16;
    float4 pa0 = *(const float4*)Ag, pa1 = *(const float4*)(Ag + 4);
    float4 pb0 = *(const float4*)Bg, pb1 = *(const float4*)(Bg + 4);
    {
        float* as = sh + arow * 20 + ak;
        as[0] = __expf(pa0.x - rm); as[1] = __expf(pa0.y - rm);
        as[2] = __expf(pa0.z - rm); as[3] = __expf(pa0.w - rm);
        as[4] = __expf(pa1.x - rm); as[5] = __expf(pa1.y - rm);
        as[6] = __expf(pa1.z - rm); as[7] = __expf(pa1.w - rm);
        float* bs = sh + 5120 + arow * 20 + ak;
        *(float4*)bs = pb0; *(float4*)(bs + 4) = pb1;
    }
    __syncthreads();
    for (int ks = 0; ks < KT; ++ks) {
        if (ks + 1 < KT) {
            const float* ag = Ag + (ks + 1) * 16;
            pa0 = *(const float4*)ag; pa1 = *(const float4*)(ag + 4);
            const float* bg = Bg + (ks + 1) * 16;
            pb0 = *(const float4*)bg; pb1 = *(const float4*)(bg + 4);
        }
        const float* As = sh + (ks & 1) * 2560;
        const float* Bs = sh + 5120 + (ks & 1) * 2560;
#pragma unroll
        for (int kk = 0; kk < 2; ++kk) {
            int kc = (kk << 3) + tg;
            unsigned a[4][4], bf[4][2];
#pragma unroll
            for (int mi = 0; mi < 4; ++mi) {
                const float* p = As + (wm + (mi << 4) + g) * 20 + kc;
                a[mi][0] = __float_as_uint(p[0]);
                a[mi][1] = __float_as_uint(p[160]);
                a[mi][2] = __float_as_uint(p[4]);
                a[mi][3] = __float_as_uint(p[164]);
            }
#pragma unroll
            for (int ni = 0; ni < 4; ++ni) {
                const float* p = Bs + (wn + (ni << 3) + g) * 20 + kc;
                bf[ni][0] = __float_as_uint(p[0]);
                bf[ni][1] = __float_as_uint(p[4]);
            }
#pragma unroll
            for (int mi = 0; mi < 4; ++mi)
#pragma unroll
                for (int ni = 0; ni < 4; ++ni) MMA_TF32(acc[mi][ni], a[mi], bf[ni]);
        }
        if (ks + 1 < KT) {
            float* as = sh + ((ks + 1) & 1) * 2560 + arow * 20 + ak;
            as[0] = __expf(pa0.x - rm); as[1] = __expf(pa0.y - rm);
            as[2] = __expf(pa0.z - rm); as[3] = __expf(pa0.w - rm);
            as[4] = __expf(pa1.x - rm); as[5] = __expf(pa1.y - rm);
            as[6] = __expf(pa1.z - rm); as[7] = __expf(pa1.w - rm);
            float* bs = sh + 5120 + ((ks + 1) & 1) * 2560 + arow * 20 + ak;
            *(float4*)bs = pb0; *(float4*)(bs + 4) = pb1;
            __syncthreads();
        }
    }
    float* Cp = Co + (size_t)b * cB;
    const float* ip = sinv + b * sstr;
#pragma unroll
    for (int mi = 0; mi < 4; ++mi)
#pragma unroll
        for (int h = 0; h < 2; ++h) {
            int row = m0 + wm + (mi << 4) + g + (h << 3);
            float sc = ip[row];
#pragma unroll
            for (int ni = 0; ni < 4; ++ni) {
                int col = n0 + wn + (ni << 3) + (tg << 1);
                float2 v = make_float2(acc[mi][ni][2 * h] * sc, acc[mi][ni][2 * h + 1] * sc);
                *(float2*)(Cp + (size_t)row * ldc + col) = v;
            }
        }
}

// ---------------- row softmax stats: warp per row -----------------------------
__global__ __launch_bounds__(256) void redmax_kernel(const float* __restrict__ src,
                                                     float* __restrict__ omax,
                                                     float* __restrict__ oinv, int cols) {
    int row = blockIdx.x * 8 + (threadIdx.x >> 5);
    int lane = threadIdx.x & 31;
    const float* p = src + (size_t)row * cols;
    float m = -1e30f;
    for (int q = lane * 4; q < cols; q += 128) {
        float4 v = *(const float4*)(p + q);
        m = fmaxf(m, fmaxf(fmaxf(v.x, v.y), fmaxf(v.z, v.w)));
    }
#pragma unroll
    for (int o = 16; o; o >>= 1) m = fmaxf(m, __shfl_xor_sync(0xffffffffu, m, o));
    float s = 0.f;
    for (int q = lane * 4; q < cols; q += 128) {
        float4 v = *(const float4*)(p + q);
        s += __expf(v.x - m) + __expf(v.y - m) + __expf(v.z - m) + __expf(v.w - m);
    }
#pragma unroll
    for (int o = 16; o; o >>= 1) s += __shfl_xor_sync(0xffffffffu, s, o);
    if (lane == 0) { omax[row] = m; oinv[row] = 1.f / s; }
}

// ---------------- output assembly: out (B, 4D, CL) ----------------------------
__global__ __launch_bounds__(256) void final_kernel(const float* __restrict__ C,
                                                    float* __restrict__ out) {
    __shared__ float tA[32][33], tB[32][33];
    int b = blockIdx.z;
    int c0 = blockIdx.x << 5, d0 = blockIdx.y << 5;
    int tx = threadIdx.x, ty = threadIdx.y;
    const float* Ap = g_Aeff + (size_t)b * CLN * DD;   // holds A = S1 @ Qt
    const float* Bp = g_Bm + (size_t)b * CLN * DD;
#pragma unroll
    for (int i = 0; i < 32; i += 8) {
        tA[ty + i][tx] = Ap[(size_t)(c0 + ty + i) * DD + d0 + tx];
        tB[ty + i][tx] = Bp[(size_t)(c0 + ty + i) * DD + d0 + tx];
    }
    __syncthreads();
    size_t ob = (size_t)b * (4 * DD) * CLN;
#pragma unroll
    for (int i = 0; i < 32; i += 8) {
        int d = d0 + ty + i, c = c0 + tx;
        float cv = C[((size_t)b * DD + d) * CLN + c];
        float av = tA[tx][ty + i];
        float bm = tB[tx][ty + i];
        out[ob + (size_t)d * CLN + c] = cv;
        out[ob + (size_t)(DD + d) * CLN + c] = av;
        out[ob + (size_t)(2 * DD + d) * CLN + c] = cv * av;
        out[ob + (size_t)(3 * DD + d) * CLN + c] = cv * bm;
    }
}

// ---------------- launch ------------------------------------------------------
extern "C" void kernel_launch(void* const* d_in, const int* in_sizes, int n_in,
                              void* d_out, int out_size) {
    const float* C = (const float*)d_in[0];
    const float* Q = (const float*)d_in[1];
    const float* W = (const float*)d_in[2];
    float* out = (float*)d_out;

    float* Ct; cudaGetSymbolAddress((void**)&Ct, g_Ct);
    float* Qt; cudaGetSymbolAddress((void**)&Qt, g_Qt);
    float* S;  cudaGetSymbolAddress((void**)&S, g_S);
    float* St; cudaGetSymbolAddress((void**)&St, g_St);
    float* rmax; cudaGetSymbolAddress((void**)&rmax, g_rmax);
    float* rinv; cudaGetSymbolAddress((void**)&rinv, g_rinv);
    float* cmax; cudaGetSymbolAddress((void**)&cmax, g_cmax);
    float* cinv; cudaGetSymbolAddress((void**)&cinv, g_cinv);
    float* T;  cudaGetSymbolAddress((void**)&T, g_T);
    float* Tt; cudaGetSymbolAddress((void**)&Tt, g_Tt);
    float* A;  cudaGetSymbolAddress((void**)&A, g_Aeff);
    float* Bm; cudaGetSymbolAddress((void**)&Bm, g_Bm);

    tr_kernel<<<dim3(CLN / 32, DD / 32, BB), dim3(32, 8)>>>(C, Ct, DD, CLN);
    tr_kernel<<<dim3(QLN / 32, DD / 32, BB), dim3(32, 8)>>>(Q, Qt, DD, QLN);
    prep_kernel<<<dim3(CLN, BB), 128>>>(W);
    gemm1_kernel<<<dim3(QLN / 128, CLN / 128, BB), 256>>>();
    redmax_kernel<<<BB * CLN / 8, 256>>>(S, rmax, rinv, QLN);
    redmax_kernel<<<BB * QLN / 8, 256>>>(St, cmax, cinv, CLN);
    // G3: T = diag(cinv) exp(St - cmax) @ C^T   (M=QL, N=D, K=CL)
    gemm_exp_kernel<<<dim3(1, QLN / 128, BB), 256>>>(
        St, CLN, (size_t)QLN * CLN, cmax, cinv, QLN,
        C, CLN, (size_t)DD * CLN, T, DD, (size_t)QLN * DD, CLN);
    tr_kernel<<<dim3(DD / 32, QLN / 32, BB), dim3(32, 8)>>>(T, Tt, QLN, DD);
    // G2: A = diag(rinv) exp(S - rmax) @ Q^T    (M=CL, N=D, K=QL)
    gemm_exp_kernel<<<dim3(1, CLN / 128, BB), 256>>>(
        S, QLN, (size_t)CLN * QLN, rmax, rinv, CLN,
        Q, QLN, (size_t)DD * QLN, A, DD, (size_t)CLN * DD, QLN);
    // G4: Bm = diag(rinv) exp(S - rmax) @ Tt^T  (M=CL, N=D, K=QL)
    gemm_exp_kernel<<<dim3(1, CLN / 128, BB), 256>>>(
        S, QLN, (size_t)CLN * QLN, rmax, rinv, CLN,
        Tt, QLN, (size_t)DD * QLN, Bm, DD, (size_t)CLN * DD, QLN);
    final_kernel<<<dim3(CLN / 32, DD / 32, BB), dim3(32, 8)>>>(C, out);
}

// round 5
// speedup vs baseline: 2.7976x; 1.0657x over previous
#include <cuda_runtime.h>
#include <cstdint>

#define BB  32
#define DD  128
#define CLN 1024
#define QLN 512

// ---------------- scratch (device globals; no allocations allowed) ----------
__device__ float g_Qt[BB * QLN * DD];           // Q^T (B, QL, D) - G1 B operand
__device__ float g_Aeff[BB * CLN * DD];         // wq + wqc*C^T ; later A = S1@Qt
__device__ float g_bias[BB * CLN];
__device__ float g_S[(size_t)BB * CLN * QLN];   // S, then exp(S - rmax)
__device__ float g_St[(size_t)BB * QLN * CLN];  // S^T, then exp(S^T - cmax)
__device__ float g_rinv[BB * CLN];
__device__ float g_cinv[BB * QLN];
__device__ float g_Tt[BB * DD * QLN];           // (S2^T C)^T  (B, D, QL)
__device__ float g_Bm[BB * CLN * DD];

// ---------------- cp.async helpers -------------------------------------------
__device__ __forceinline__ uint32_t s2u(const void* p) {
    uint32_t a;
    asm("{ .reg .u64 t; cvta.to.shared.u64 t, %1; cvt.u32.u64 %0, t; }" : "=r"(a) : "l"(p));
    return a;
}
#define CPC()  asm volatile("cp.async.commit_group;" ::: "memory")
#define CPW0() asm volatile("cp.async.wait_group 0;" ::: "memory")

// fill one stage: 128 rows x 16 floats, row stride 20 floats (80B), 2 ops/thread
__device__ __forceinline__ void cfill(uint32_t sb, const float* __restrict__ g,
                                      int ld, int row0, int k0, int t) {
#pragma unroll
    for (int j = 0; j < 2; ++j) {
        int lin = t + (j << 8);
        int r = lin >> 2, q = lin & 3;
        asm volatile("cp.async.cg.shared.global [%0], [%1], 16;"
                     :: "r"(sb + r * 80 + q * 16),
                        "l"(g + (size_t)(row0 + r) * ld + k0 + (q << 2)));
    }
}

// ---------------- mma.sync tf32 ----------------------------------------------
#define MMA_TF32(D, A, B)                                                          \
    asm volatile(                                                                  \
        "mma.sync.aligned.m16n8k8.row.col.f32.tf32.tf32.f32 "                      \
        "{%0,%1,%2,%3}, {%4,%5,%6,%7}, {%8,%9}, {%0,%1,%2,%3};"                    \
        : "+f"((D)[0]), "+f"((D)[1]), "+f"((D)[2]), "+f"((D)[3])                   \
        : "r"((A)[0]), "r"((A)[1]), "r"((A)[2]), "r"((A)[3]),                      \
          "r"((B)[0]), "r"((B)[1]))

// one 16-wide K chunk: 2 kk-steps, 16 MMAs each; As/Bs row-major stride 20
__device__ __forceinline__ void mma_chunk(const float* __restrict__ As,
                                          const float* __restrict__ Bs,
                                          float acc[4][4][4],
                                          int wm, int wn, int g, int tg) {
#pragma unroll
    for (int kk = 0; kk < 2; ++kk) {
        int kc = (kk << 3) + tg;
        unsigned a[4][4], bf[4][2];
#pragma unroll
        for (int mi = 0; mi < 4; ++mi) {
            const float* p = As + (wm + (mi << 4) + g) * 20 + kc;
            a[mi][0] = __float_as_uint(p[0]);
            a[mi][1] = __float_as_uint(p[160]);
            a[mi][2] = __float_as_uint(p[4]);
            a[mi][3] = __float_as_uint(p[164]);
        }
#pragma unroll
        for (int ni = 0; ni < 4; ++ni) {
            const float* p = Bs + (wn + (ni << 3) + g) * 20 + kc;
            bf[ni][0] = __float_as_uint(p[0]);
            bf[ni][1] = __float_as_uint(p[4]);
        }
#pragma unroll
        for (int mi = 0; mi < 4; ++mi)
#pragma unroll
            for (int ni = 0; ni < 4; ++ni) MMA_TF32(acc[mi][ni], a[mi], bf[ni]);
    }
}

// ---------------- tr (Q only): in (B,R,L) -> out (B,L,R) ----------------------
__global__ __launch_bounds__(256) void tr_kernel(const float* __restrict__ in,
                                                 float* __restrict__ out, int R, int L) {
    __shared__ float t[32][33];
    int b = blockIdx.z;
    int l0 = blockIdx.x << 5, r0 = blockIdx.y << 5;
    int tx = threadIdx.x, ty = threadIdx.y;
    const float* ip = in + (size_t)b * R * L;
    float* op = out + (size_t)b * R * L;
#pragma unroll
    for (int i = 0; i < 32; i += 8) t[ty + i][tx] = ip[(size_t)(r0 + ty + i) * L + l0 + tx];
    __syncthreads();
#pragma unroll
    for (int i = 0; i < 32; i += 8) op[(size_t)(l0 + ty + i) * R + r0 + tx] = t[tx][ty + i];
}

// ---------------- prep fused with C transpose ---------------------------------
// block: 128 threads, 32 c-values; Aeff = wq + wqc*ct ; bias = sum_d wc*ct
__global__ __launch_bounds__(128) void prepC_kernel(const float* __restrict__ C,
                                                    const float* __restrict__ W) {
    __shared__ float tile[128][33];
    __shared__ float red[4];
    int b = blockIdx.y, c0 = blockIdx.x << 5;
    int t = threadIdx.x, warp = t >> 5, lane = t & 31;
    for (int d = warp; d < 128; d += 4)
        tile[d][lane] = C[((size_t)b * DD + d) * CLN + c0 + lane];
    __syncthreads();
    for (int cc = 0; cc < 32; ++cc) {
        int c = c0 + cc;
        size_t rc = (size_t)b * CLN + c;
        const float* w = W + rc * (3 * DD);
        float ct = tile[t][cc];
        g_Aeff[(rc << 7) + t] = w[t] + w[2 * DD + t] * ct;
        float v = w[DD + t] * ct;
#pragma unroll
        for (int o = 16; o; o >>= 1) v += __shfl_xor_sync(0xffffffffu, v, o);
        if (lane == 0) red[warp] = v;
        __syncthreads();
        if (t == 0) g_bias[rc] = red[0] + red[1] + red[2] + red[3];
        __syncthreads();
    }
}

// ---------------- softmax stats + in-place exp --------------------------------
__global__ __launch_bounds__(256) void redexp_kernel(float* __restrict__ src,
                                                     float* __restrict__ oinv, int cols) {
    int row = blockIdx.x * 8 + (threadIdx.x >> 5);
    int lane = threadIdx.x & 31;
    float* p = src + (size_t)row * cols;
    float m = -1e30f;
    for (int q = lane * 4; q < cols; q += 128) {
        float4 v = *(const float4*)(p + q);
        m = fmaxf(m, fmaxf(fmaxf(v.x, v.y), fmaxf(v.z, v.w)));
    }
#pragma unroll
    for (int o = 16; o; o >>= 1) m = fmaxf(m, __shfl_xor_sync(0xffffffffu, m, o));
    float s = 0.f;
    for (int q = lane * 4; q < cols; q += 128) {
        float4 v = *(const float4*)(p + q);
        v.x = __expf(v.x - m); v.y = __expf(v.y - m);
        v.z = __expf(v.z - m); v.w = __expf(v.w - m);
        s += v.x + v.y + v.z + v.w;
        *(float4*)(p + q) = v;
    }
#pragma unroll
    for (int o = 16; o; o >>= 1) s += __shfl_xor_sync(0xffffffffu, s, o);
    if (lane == 0) oinv[row] = 1.f / s;
}

// ---------------- G1: S = Aeff @ Qt^T + bias ; writes S and S^T ---------------
__global__ __launch_bounds__(256) void g1_mma() {
    __shared__ float sm[10240];  // A: 2x2560 floats, B: 2x2560 (stride 20)
    int b = blockIdx.z, n0 = blockIdx.x << 7, m0 = blockIdx.y << 7;
    const float* A = g_Aeff + (size_t)b * CLN * DD;
    const float* Bq = g_Qt + (size_t)b * QLN * DD;
    uint32_t su = s2u(sm);
    int t = threadIdx.x, lane = t & 31, warp = t >> 5;
    int g = lane >> 2, tg = lane & 3;
    int wm = (warp >> 2) << 6, wn = (warp & 3) << 5;
    float acc[4][4][4] = {};
    const int KT = DD / 16;
    cfill(su, A, DD, m0, 0, t);
    cfill(su + 20480, Bq, DD, n0, 0, t);
    CPC();
    for (int i = 0; i < KT; ++i) {
        CPW0();
        __syncthreads();
        if (i + 1 < KT) {
            int s = (i + 1) & 1;
            cfill(su + s * 10240, A, DD, m0, (i + 1) * 16, t);
            cfill(su + 20480 + s * 10240, Bq, DD, n0, (i + 1) * 16, t);
            CPC();
        }
        mma_chunk(sm + (i & 1) * 2560, sm + 5120 + (i & 1) * 2560, acc, wm, wn, g, tg);
    }
    // epilogue: S (+bias) direct, S^T via smem staging
    float* Sp = g_S + (size_t)b * CLN * QLN;
    float* Stp = g_St + (size_t)b * QLN * CLN;
    const float* bp = g_bias + b * CLN;
#pragma unroll
    for (int mi = 0; mi < 4; ++mi)
#pragma unroll
        for (int h = 0; h < 2; ++h) {
            int row = m0 + wm + (mi << 4) + g + (h << 3);
            float bbv = bp[row];
#pragma unroll
            for (int ni = 0; ni < 4; ++ni) {
                int col = n0 + wn + (ni << 3) + (tg << 1);
                float2 v = make_float2(acc[mi][ni][2 * h] + bbv, acc[mi][ni][2 * h + 1] + bbv);
                *(float2*)(Sp + (size_t)row * QLN + col) = v;
            }
        }
    for (int ch = 0; ch < 4; ++ch) {
        __syncthreads();
        if ((ch >> 1) == (warp >> 2)) {
            int mi0 = (ch & 1) << 1;
#pragma unroll
            for (int mm = 0; mm < 2; ++mm) {
                int mi = mi0 + mm;
#pragma unroll
                for (int h = 0; h < 2; ++h) {
                    int ml = (mm << 4) + g + (h << 3);
                    int row = m0 + wm + (mi << 4) + g + (h << 3);
                    float bbv = bp[row];
#pragma unroll
                    for (int ni = 0; ni < 4; ++ni) {
                        int n = wn + (ni << 3) + (tg << 1);
                        sm[ml * 133 + n] = acc[mi][ni][2 * h] + bbv;
                        sm[ml * 133 + n + 1] = acc[mi][ni][2 * h + 1] + bbv;
                    }
                }
            }
        }
        __syncthreads();
        int cl = t & 31, qw = t >> 5;
#pragma unroll
        for (int i = 0; i < 16; ++i) {
            int qq = qw + (i << 3);
            Stp[(size_t)(n0 + qq) * CLN + m0 + (ch << 5) + cl] = sm[cl * 133 + qq];
        }
    }
}

// ---------------- G3: Tt = (diag(cinv) expSt @ C^T)^T -------------------------
// M=QL tile 128, N=D=128, K=CL=1024 ; writes transposed output directly
__global__ __launch_bounds__(256) void g3_mma(const float* __restrict__ Cin) {
    __shared__ float sm[10240];
    int b = blockIdx.y, m0 = blockIdx.x << 7;
    const float* A = g_St + (size_t)b * QLN * CLN;     // exp'd
    const float* Bp = Cin + (size_t)b * DD * CLN;
    uint32_t su = s2u(sm);
    int t = threadIdx.x, lane = t & 31, warp = t >> 5;
    int g = lane >> 2, tg = lane & 3;
    int wm = (warp >> 2) << 6, wn = (warp & 3) << 5;
    float acc[4][4][4] = {};
    const int KT = CLN / 16;
    cfill(su, A, CLN, m0, 0, t);
    cfill(su + 20480, Bp, CLN, 0, 0, t);
    CPC();
    for (int i = 0; i < KT; ++i) {
        CPW0();
        __syncthreads();
        if (i + 1 < KT) {
            int s = (i + 1) & 1;
            cfill(su + s * 10240, A, CLN, m0, (i + 1) * 16, t);
            cfill(su + 20480 + s * 10240, Bp, CLN, 0, (i + 1) * 16, t);
            CPC();
        }
        mma_chunk(sm + (i & 1) * 2560, sm + 5120 + (i & 1) * 2560, acc, wm, wn, g, tg);
    }
    // transposed epilogue via smem staging: Tt[d][q]
    float* Ttp = g_Tt + (size_t)b * DD * QLN;
    const float* ip = g_cinv + b * QLN;
    for (int ch = 0; ch < 4; ++ch) {
        __syncthreads();
        if ((ch >> 1) == (warp >> 2)) {
            int mi0 = (ch & 1) << 1;
#pragma unroll
            for (int mm = 0; mm < 2; ++mm) {
                int mi = mi0 + mm;
#pragma unroll
                for (int h = 0; h < 2; ++h) {
                    int ml = (mm << 4) + g + (h << 3);
                    int row = m0 + wm + (mi << 4) + g + (h << 3);
                    float sc = ip[row];
#pragma unroll
                    for (int ni = 0; ni < 4; ++ni) {
                        int n = wn + (ni << 3) + (tg << 1);
                        sm[ml * 133 + n] = acc[mi][ni][2 * h] * sc;
                        sm[ml * 133 + n + 1] = acc[mi][ni][2 * h + 1] * sc;
                    }
                }
            }
        }
        __syncthreads();
        int cl = t & 31, dw = t >> 5;
#pragma unroll
        for (int i = 0; i < 16; ++i) {
            int d = dw + (i << 3);
            Ttp[(size_t)d * QLN + m0 + (ch << 5) + cl] = sm[cl * 133 + d];
        }
    }
}

// ---------------- G2/G4: Co = diag(rinv) * expS @ Bop^T -----------------------
// M=CL tile 128, N=D=128, K=QL=512 ; Bop: (B, D, QL) K-contiguous
__global__ __launch_bounds__(256) void gA_mma(const float* __restrict__ Bop,
                                              float* __restrict__ Co) {
    __shared__ float sm[10240];
    int b = blockIdx.y, m0 = blockIdx.x << 7;
    const float* A = g_S + (size_t)b * CLN * QLN;      // exp'd
    const float* Bp = Bop + (size_t)b * DD * QLN;
    uint32_t su = s2u(sm);
    int t = threadIdx.x, lane = t & 31, warp = t >> 5;
    int g = lane >> 2, tg = lane & 3;
    int wm = (warp >> 2) << 6, wn = (warp & 3) << 5;
    float acc[4][4][4] = {};
    const int KT = QLN / 16;
    cfill(su, A, QLN, m0, 0, t);
    cfill(su + 20480, Bp, QLN, 0, 0, t);
    CPC();
    for (int i = 0; i < KT; ++i) {
        CPW0();
        __syncthreads();
        if (i + 1 < KT) {
            int s = (i + 1) & 1;
            cfill(su + s * 10240, A, QLN, m0, (i + 1) * 16, t);
            cfill(su + 20480 + s * 10240, Bp, QLN, 0, (i + 1) * 16, t);
            CPC();
        }
        mma_chunk(sm + (i & 1) * 2560, sm + 5120 + (i & 1) * 2560, acc, wm, wn, g, tg);
    }
    float* Cp = Co + (size_t)b * CLN * DD;
    const float* ip = g_rinv + b * CLN;
#pragma unroll
    for (int mi = 0; mi < 4; ++mi)
#pragma unroll
        for (int h = 0; h < 2; ++h) {
            int row = m0 + wm + (mi << 4) + g + (h << 3);
            float sc = ip[row];
#pragma unroll
            for (int ni = 0; ni < 4; ++ni) {
                int col = wn + (ni << 3) + (tg << 1);
                float2 v = make_float2(acc[mi][ni][2 * h] * sc, acc[mi][ni][2 * h + 1] * sc);
                *(float2*)(Cp + (size_t)row * DD + col) = v;
            }
        }
}

// ---------------- output assembly: out (B, 4D, CL) ----------------------------
__global__ __launch_bounds__(256) void final_kernel(const float* __restrict__ C,
                                                    float* __restrict__ out) {
    __shared__ float tA[32][33], tB[32][33];
    int b = blockIdx.z;
    int c0 = blockIdx.x << 5, d0 = blockIdx.y << 5;
    int tx = threadIdx.x, ty = threadIdx.y;
    const float* Ap = g_Aeff + (size_t)b * CLN * DD;   // holds A = S1 @ Qt
    const float* Bp = g_Bm + (size_t)b * CLN * DD;
#pragma unroll
    for (int i = 0; i < 32; i += 8) {
        tA[ty + i][tx] = Ap[(size_t)(c0 + ty + i) * DD + d0 + tx];
        tB[ty + i][tx] = Bp[(size_t)(c0 + ty + i) * DD + d0 + tx];
    }
    __syncthreads();
    size_t ob = (size_t)b * (4 * DD) * CLN;
#pragma unroll
    for (int i = 0; i < 32; i += 8) {
        int d = d0 + ty + i, c = c0 + tx;
        float cv = C[((size_t)b * DD + d) * CLN + c];
        float av = tA[tx][ty + i];
        float bm = tB[tx][ty + i];
        out[ob + (size_t)d * CLN + c] = cv;
        out[ob + (size_t)(DD + d) * CLN + c] = av;
        out[ob + (size_t)(2 * DD + d) * CLN + c] = cv * av;
        out[ob + (size_t)(3 * DD + d) * CLN + c] = cv * bm;
    }
}

// ---------------- launch ------------------------------------------------------
extern "C" void kernel_launch(void* const* d_in, const int* in_sizes, int n_in,
                              void* d_out, int out_size) {
    const float* C = (const float*)d_in[0];
    const float* Q = (const float*)d_in[1];
    const float* W = (const float*)d_in[2];
    float* out = (float*)d_out;

    float* Qt; cudaGetSymbolAddress((void**)&Qt, g_Qt);
    float* S;  cudaGetSymbolAddress((void**)&S, g_S);
    float* St; cudaGetSymbolAddress((void**)&St, g_St);
    float* rinv; cudaGetSymbolAddress((void**)&rinv, g_rinv);
    float* cinv; cudaGetSymbolAddress((void**)&cinv, g_cinv);
    float* Tt; cudaGetSymbolAddress((void**)&Tt, g_Tt);
    float* A;  cudaGetSymbolAddress((void**)&A, g_Aeff);
    float* Bm; cudaGetSymbolAddress((void**)&Bm, g_Bm);

    tr_kernel<<<dim3(QLN / 32, DD / 32, BB), dim3(32, 8)>>>(Q, Qt, DD, QLN);
    prepC_kernel<<<dim3(CLN / 32, BB), 128>>>(C, W);
    g1_mma<<<dim3(QLN / 128, CLN / 128, BB), 256>>>();
    redexp_kernel<<<BB * CLN / 8, 256>>>(S, rinv, QLN);     // rows of S (q-dim)
    redexp_kernel<<<BB * QLN / 8, 256>>>(St, cinv, CLN);    // rows of S^T (c-dim)
    g3_mma<<<dim3(QLN / 128, BB), 256>>>(C);                // Tt
    gA_mma<<<dim3(CLN / 128, BB), 256>>>(Q, A);             // A  = S1 @ Qt
    gA_mma<<<dim3(CLN / 128, BB), 256>>>(Tt, Bm);           // Bm = S1 @ S2tC
    final_kernel<<<dim3(CLN / 32, DD / 32, BB), dim3(32, 8)>>>(C, out);
}

// round 7
// speedup vs baseline: 3.2445x; 1.1597x over previous
#include <cuda_runtime.h>
#include <cstdint>

#define BB  32
#define DD  128
#define CLN 1024
#define QLN 512

// ---------------- scratch (device globals; no allocations allowed) ----------
__device__ float g_Aeff[BB * CLN * DD];         // wq + wqc*C^T
__device__ float g_bias[BB * CLN];
__device__ float g_S[(size_t)BB * CLN * QLN];   // exp(S)  (B, CL, QL)
__device__ float g_rsum[BB * CLN];              // row sums -> reciprocals
__device__ float g_csum[BB * QLN];              // col sums -> reciprocals
__device__ float g_Tt[BB * DD * QLN];           // (S2^T C)^T  (B, D, QL)

// ---------------- helpers -----------------------------------------------------
__device__ __forceinline__ uint32_t s2u(const void* p) {
    uint32_t a;
    asm("{ .reg .u64 t; cvta.to.shared.u64 t, %1; cvt.u32.u64 %0, t; }" : "=r"(a) : "l"(p));
    return a;
}
#define CPC()  asm volatile("cp.async.commit_group;" ::: "memory")
#define CPW0() asm volatile("cp.async.wait_group 0;" ::: "memory")

// cp.async fill: 128 rows x 16 floats, row stride 20 floats
__device__ __forceinline__ void cfill(uint32_t sb, const float* __restrict__ g,
                                      int ld, int row0, int k0, int t) {
#pragma unroll
    for (int j = 0; j < 2; ++j) {
        int lin = t + (j << 8);
        int r = lin >> 2, q = lin & 3;
        asm volatile("cp.async.cg.shared.global [%0], [%1], 16;"
                     :: "r"(sb + r * 80 + q * 16),
                        "l"(g + (size_t)(row0 + r) * ld + k0 + (q << 2)));
    }
}

// transposed fill (LDG part): src [k][n] row-major ld; chunk = 16 k-rows x 128 n
__device__ __forceinline__ void tload(const float* __restrict__ g, int ld,
                                      int n0, int k0, int t, float v[8]) {
    int q = t & 127, cs = (t >> 7) << 3;
#pragma unroll
    for (int i = 0; i < 8; ++i)
        v[i] = g[(size_t)(k0 + cs + i) * ld + n0 + q];
}
// STS part: smem [n][k] stride 20
__device__ __forceinline__ void tstore(float* smf, int t, const float v[8]) {
    int q = t & 127, cs = (t >> 7) << 3;
#pragma unroll
    for (int i = 0; i < 8; ++i) smf[q * 20 + cs + i] = v[i];
}

// ---------------- mma.sync tf32 ----------------------------------------------
#define MMA_TF32(D, A, B)                                                          \
    asm volatile(                                                                  \
        "mma.sync.aligned.m16n8k8.row.col.f32.tf32.tf32.f32 "                      \
        "{%0,%1,%2,%3}, {%4,%5,%6,%7}, {%8,%9}, {%0,%1,%2,%3};"                    \
        : "+f"((D)[0]), "+f"((D)[1]), "+f"((D)[2]), "+f"((D)[3])                   \
        : "r"((A)[0]), "r"((A)[1]), "r"((A)[2]), "r"((A)[3]),                      \
          "r"((B)[0]), "r"((B)[1]))

__device__ __forceinline__ void mma_chunk(const float* __restrict__ As,
                                          const float* __restrict__ Bs,
                                          float acc[4][4][4],
                                          int wm, int wn, int g, int tg) {
#pragma unroll
    for (int kk = 0; kk < 2; ++kk) {
        int kc = (kk << 3) + tg;
        unsigned a[4][4], bf[4][2];
#pragma unroll
        for (int mi = 0; mi < 4; ++mi) {
            const float* p = As + (wm + (mi << 4) + g) * 20 + kc;
            a[mi][0] = __float_as_uint(p[0]);
            a[mi][1] = __float_as_uint(p[160]);
            a[mi][2] = __float_as_uint(p[4]);
            a[mi][3] = __float_as_uint(p[164]);
        }
#pragma unroll
        for (int ni = 0; ni < 4; ++ni) {
            const float* p = Bs + (wn + (ni << 3) + g) * 20 + kc;
            bf[ni][0] = __float_as_uint(p[0]);
            bf[ni][1] = __float_as_uint(p[4]);
        }
#pragma unroll
        for (int mi = 0; mi < 4; ++mi)
#pragma unroll
            for (int ni = 0; ni < 4; ++ni) MMA_TF32(acc[mi][ni], a[mi], bf[ni]);
    }
}

// ---------------- prep fused with C transpose ---------------------------------
__global__ __launch_bounds__(128) void prepC_kernel(const float* __restrict__ C,
                                                    const float* __restrict__ W) {
    __shared__ float tile[128][33];
    __shared__ float red[4];
    int b = blockIdx.y, c0 = blockIdx.x << 5;
    int t = threadIdx.x, warp = t >> 5, lane = t & 31;
    for (int d = warp; d < 128; d += 4)
        tile[d][lane] = C[((size_t)b * DD + d) * CLN + c0 + lane];
    __syncthreads();
    for (int cc = 0; cc < 32; ++cc) {
        int c = c0 + cc;
        size_t rc = (size_t)b * CLN + c;
        const float* w = W + rc * (3 * DD);
        float ct = tile[t][cc];
        g_Aeff[(rc << 7) + t] = w[t] + w[2 * DD + t] * ct;
        float v = w[DD + t] * ct;
#pragma unroll
        for (int o = 16; o; o >>= 1) v += __shfl_xor_sync(0xffffffffu, v, o);
        if (lane == 0) red[warp] = v;
        __syncthreads();
        if (t == 0) g_bias[rc] = red[0] + red[1] + red[2] + red[3];
        __syncthreads();
    }
}

// ---------------- tiny kernels: zero sums / reciprocal ------------------------
__global__ __launch_bounds__(256) void zero_kernel() {
    int i = blockIdx.x * 256 + threadIdx.x;
    if (i < BB * CLN) g_rsum[i] = 0.f;
    if (i < BB * QLN) g_csum[i] = 0.f;
}
__global__ __launch_bounds__(256) void inv_kernel() {
    int i = blockIdx.x * 256 + threadIdx.x;
    if (i < BB * CLN) g_rsum[i] = 1.f / g_rsum[i];
    if (i < BB * QLN) g_csum[i] = 1.f / g_csum[i];
}

// ---------------- G1: expS = exp(Aeff @ Q + bias); row/col sums via atomics ---
// M=CL tile 128, N=QL tile 128, K=D=128 ; B loaded transposed from Q [d][q]
__global__ __launch_bounds__(256) void g1_mma(const float* __restrict__ Qin) {
    __shared__ float sm[10240];
    int b = blockIdx.z, n0 = blockIdx.x << 7, m0 = blockIdx.y << 7;
    const float* A = g_Aeff + (size_t)b * CLN * DD;
    const float* Qp = Qin + (size_t)b * DD * QLN;
    uint32_t su = s2u(sm);
    int t = threadIdx.x, lane = t & 31, warp = t >> 5;
    int g = lane >> 2, tg = lane & 3;
    int wm = (warp >> 2) << 6, wn = (warp & 3) << 5;
    float acc[4][4][4] = {};
    const int KT = DD / 16;
    float bv[8];
    cfill(su, A, DD, m0, 0, t);
    tload(Qp, QLN, n0, 0, t, bv);
    tstore(sm + 5120, t, bv);
    CPC();
    for (int i = 0; i < KT; ++i) {
        if (i + 1 < KT) tload(Qp, QLN, n0, (i + 1) * 16, t, bv);
        CPW0();
        __syncthreads();
        if (i + 1 < KT) {
            int s = (i + 1) & 1;
            cfill(su + s * 10240, A, DD, m0, (i + 1) * 16, t);
            tstore(sm + 5120 + s * 2560, t, bv);
            CPC();
        }
        mma_chunk(sm + (i & 1) * 2560, sm + 5120 + (i & 1) * 2560, acc, wm, wn, g, tg);
    }
    // exp (with bias) in place
    const float* bp = g_bias + b * CLN + m0;
#pragma unroll
    for (int mi = 0; mi < 4; ++mi)
#pragma unroll
        for (int h = 0; h < 2; ++h) {
            float bbv = bp[wm + (mi << 4) + g + (h << 3)];
#pragma unroll
            for (int ni = 0; ni < 4; ++ni) {
                acc[mi][ni][2 * h] = __expf(acc[mi][ni][2 * h] + bbv);
                acc[mi][ni][2 * h + 1] = __expf(acc[mi][ni][2 * h + 1] + bbv);
            }
        }
    // write expS
    float* Sp = g_S + (size_t)b * CLN * QLN;
#pragma unroll
    for (int mi = 0; mi < 4; ++mi)
#pragma unroll
        for (int h = 0; h < 2; ++h) {
            int row = m0 + wm + (mi << 4) + g + (h << 3);
#pragma unroll
            for (int ni = 0; ni < 4; ++ni) {
                int col = n0 + wn + (ni << 3) + (tg << 1);
                *(float2*)(Sp + (size_t)row * QLN + col) =
                    make_float2(acc[mi][ni][2 * h], acc[mi][ni][2 * h + 1]);
            }
        }
    // row sums (reduce over tg lanes)
    {
        float rs[4][2];
#pragma unroll
        for (int mi = 0; mi < 4; ++mi)
#pragma unroll
            for (int h = 0; h < 2; ++h) {
                float s = 0.f;
#pragma unroll
                for (int ni = 0; ni < 4; ++ni) s += acc[mi][ni][2 * h] + acc[mi][ni][2 * h + 1];
                rs[mi][h] = s;
            }
#pragma unroll
        for (int o = 1; o <= 2; o <<= 1)
#pragma unroll
            for (int mi = 0; mi < 4; ++mi)
#pragma unroll
                for (int h = 0; h < 2; ++h)
                    rs[mi][h] += __shfl_xor_sync(0xffffffffu, rs[mi][h], o);
        if (tg == 0) {
            float* rp = g_rsum + b * CLN + m0;
#pragma unroll
            for (int mi = 0; mi < 4; ++mi)
#pragma unroll
                for (int h = 0; h < 2; ++h)
                    atomicAdd(rp + wm + (mi << 4) + g + (h << 3), rs[mi][h]);
        }
    }
    // col sums (reduce over g lanes)
    {
        float cs[4][2];
#pragma unroll
        for (int ni = 0; ni < 4; ++ni)
#pragma unroll
            for (int p = 0; p < 2; ++p) {
                float s = 0.f;
#pragma unroll
                for (int mi = 0; mi < 4; ++mi) s += acc[mi][ni][p] + acc[mi][ni][2 + p];
                cs[ni][p] = s;
            }
#pragma unroll
        for (int o = 4; o <= 16; o <<= 1)
#pragma unroll
            for (int ni = 0; ni < 4; ++ni)
#pragma unroll
                for (int p = 0; p < 2; ++p)
                    cs[ni][p] += __shfl_xor_sync(0xffffffffu, cs[ni][p], o);
        if (g == 0) {
            float* cp = g_csum + b * QLN + n0;
#pragma unroll
            for (int ni = 0; ni < 4; ++ni)
#pragma unroll
                for (int p = 0; p < 2; ++p)
                    atomicAdd(cp + wn + (ni << 3) + (tg << 1) + p, cs[ni][p]);
        }
    }
}

// ---------------- G3: Tt[d][q] = sum_c C[d][c] expS[c][q] * cinv[q] -----------
// M=D=128 (one tile), N=QL tile 128, K=CL=1024 ; B transposed from expS
__global__ __launch_bounds__(256) void g3_mma(const float* __restrict__ Cin) {
    __shared__ float sm[10240];
    int b = blockIdx.y, n0 = blockIdx.x << 7;
    const float* Ap = Cin + (size_t)b * DD * CLN;
    const float* Ep = g_S + (size_t)b * CLN * QLN;
    uint32_t su = s2u(sm);
    int t = threadIdx.x, lane = t & 31, warp = t >> 5;
    int g = lane >> 2, tg = lane & 3;
    int wm = (warp >> 2) << 6, wn = (warp & 3) << 5;
    float acc[4][4][4] = {};
    const int KT = CLN / 16;
    float bv[8];
    cfill(su, Ap, CLN, 0, 0, t);
    tload(Ep, QLN, n0, 0, t, bv);
    tstore(sm + 5120, t, bv);
    CPC();
    for (int i = 0; i < KT; ++i) {
        if (i + 1 < KT) tload(Ep, QLN, n0, (i + 1) * 16, t, bv);
        CPW0();
        __syncthreads();
        if (i + 1 < KT) {
            int s = (i + 1) & 1;
            cfill(su + s * 10240, Ap, CLN, 0, (i + 1) * 16, t);
            tstore(sm + 5120 + s * 2560, t, bv);
            CPC();
        }
        mma_chunk(sm + (i & 1) * 2560, sm + 5120 + (i & 1) * 2560, acc, wm, wn, g, tg);
    }
    float* Ttp = g_Tt + (size_t)b * DD * QLN;
    const float* ci = g_csum + b * QLN + n0;  // reciprocals
#pragma unroll
    for (int mi = 0; mi < 4; ++mi)
#pragma unroll
        for (int h = 0; h < 2; ++h) {
            int d = wm + (mi << 4) + g + (h << 3);
#pragma unroll
            for (int ni = 0; ni < 4; ++ni) {
                int col = wn + (ni << 3) + (tg << 1);
                float2 v = make_float2(acc[mi][ni][2 * h] * ci[col],
                                       acc[mi][ni][2 * h + 1] * ci[col + 1]);
                *(float2*)(Ttp + (size_t)d * QLN + n0 + col) = v;
            }
        }
}

// ---------------- G2: out blocks 0/1/2 ; G4: out block 3 ----------------------
// M=CL tile 128, N=D=128, K=QL=512 ; A = expS, B = Bop [d][q]
__global__ __launch_bounds__(256) void g2_mma(const float* __restrict__ Qin,
                                              const float* __restrict__ Cin,
                                              float* __restrict__ out) {
    __shared__ float sm[10240];
    int b = blockIdx.y, m0 = blockIdx.x << 7;
    const float* A = g_S + (size_t)b * CLN * QLN;
    const float* Bp = Qin + (size_t)b * DD * QLN;
    uint32_t su = s2u(sm);
    int t = threadIdx.x, lane = t & 31, warp = t >> 5;
    int g = lane >> 2, tg = lane & 3;
    int wm = (warp >> 2) << 6, wn = (warp & 3) << 5;
    float acc[4][4][4] = {};
    const int KT = QLN / 16;
    cfill(su, A, QLN, m0, 0, t);
    cfill(su + 20480, Bp, QLN, 0, 0, t);
    CPC();
    for (int i = 0; i < KT; ++i) {
        CPW0();
        __syncthreads();
        if (i + 1 < KT) {
            int s = (i + 1) & 1;
            cfill(su + s * 10240, A, QLN, m0, (i + 1) * 16, t);
            cfill(su + 20480 + s * 10240, Bp, QLN, 0, (i + 1) * 16, t);
            CPC();
        }
        mma_chunk(sm + (i & 1) * 2560, sm + 5120 + (i & 1) * 2560, acc, wm, wn, g, tg);
    }
    const float* ri = g_rsum + b * CLN + m0;  // reciprocals
    size_t ob = (size_t)b * (4 * DD) * CLN;
    for (int ch = 0; ch < 4; ++ch) {
        __syncthreads();
        if ((ch >> 1) == (warp >> 2)) {
            int mi0 = (ch & 1) << 1;
#pragma unroll
            for (int mm = 0; mm < 2; ++mm) {
                int mi = mi0 + mm;
#pragma unroll
                for (int h = 0; h < 2; ++h) {
                    int ml = (mm << 4) + g + (h << 3);
                    float sc = ri[wm + (mi << 4) + g + (h << 3)];
#pragma unroll
                    for (int ni = 0; ni < 4; ++ni) {
                        int n = wn + (ni << 3) + (tg << 1);
                        sm[ml * 133 + n] = acc[mi][ni][2 * h] * sc;
                        sm[ml * 133 + n + 1] = acc[mi][ni][2 * h + 1] * sc;
                    }
                }
            }
        }
        __syncthreads();
        int cl = t & 31, dw = t >> 5;
        int c = m0 + (ch << 5) + cl;
#pragma unroll
        for (int i = 0; i < 16; ++i) {
            int d = dw + (i << 3);
            float v = sm[cl * 133 + d];
            float cv = Cin[((size_t)b * DD + d) * CLN + c];
            out[ob + (size_t)d * CLN + c] = cv;
            out[ob + (size_t)(DD + d) * CLN + c] = v;
            out[ob + (size_t)(2 * DD + d) * CLN + c] = cv * v;
        }
    }
}

__global__ __launch_bounds__(256) void g4_mma(const float* __restrict__ Cin,
                                              float* __restrict__ out) {
    __shared__ float sm[10240];
    int b = blockIdx.y, m0 = blockIdx.x << 7;
    const float* A = g_S + (size_t)b * CLN * QLN;
    const float* Bp = g_Tt + (size_t)b * DD * QLN;
    uint32_t su = s2u(sm);
    int t = threadIdx.x, lane = t & 31, warp = t >> 5;
    int g = lane >> 2, tg = lane & 3;
    int wm = (warp >> 2) << 6, wn = (warp & 3) << 5;
    float acc[4][4][4] = {};
    const int KT = QLN / 16;
    cfill(su, A, QLN, m0, 0, t);
    cfill(su + 20480, Bp, QLN, 0, 0, t);
    CPC();
    for (int i = 0; i < KT; ++i) {
        CPW0();
        __syncthreads();
        if (i + 1 < KT) {
            int s = (i + 1) & 1;
            cfill(su + s * 10240, A, QLN, m0, (i + 1) * 16, t);
            cfill(su + 20480 + s * 10240, Bp, QLN, 0, (i + 1) * 16, t);
            CPC();
        }
        mma_chunk(sm + (i & 1) * 2560, sm + 5120 + (i & 1) * 2560, acc, wm, wn, g, tg);
    }
    const float* ri = g_rsum + b * CLN + m0;
    size_t ob = (size_t)b * (4 * DD) * CLN;
    for (int ch = 0; ch < 4; ++ch) {
        __syncthreads();
        if ((ch >> 1) == (warp >> 2)) {
            int mi0 = (ch & 1) << 1;
#pragma unroll
            for (int mm = 0; mm < 2; ++mm) {
                int mi = mi0 + mm;
#pragma unroll
                for (int h = 0; h < 2; ++h) {
                    int ml = (mm << 4) + g + (h << 3);
                    float sc = ri[wm + (mi << 4) + g + (h << 3)];
#pragma unroll
                    for (int ni = 0; ni < 4; ++ni) {
                        int n = wn + (ni << 3) + (tg << 1);
                        sm[ml * 133 + n] = acc[mi][ni][2 * h] * sc;
                        sm[ml * 133 + n + 1] = acc[mi][ni][2 * h + 1] * sc;
                    }
                }
            }
        }
        __syncthreads();
        int cl = t & 31, dw = t >> 5;
        int c = m0 + (ch << 5) + cl;
#pragma unroll
        for (int i = 0; i < 16; ++i) {
            int d = dw + (i << 3);
            float v = sm[cl * 133 + d];
            float cv = Cin[((size_t)b * DD + d) * CLN + c];
            out[ob + (size_t)(3 * DD + d) * CLN + c] = cv * v;
        }
    }
}

// ---------------- launch ------------------------------------------------------
extern "C" void kernel_launch(void* const* d_in, const int* in_sizes, int n_in,
                              void* d_out, int out_size) {
    const float* C = (const float*)d_in[0];
    const float* Q = (const float*)d_in[1];
    const float* W = (const float*)d_in[2];
    float* out = (float*)d_out;

    zero_kernel<<<192, 256>>>();
    prepC_kernel<<<dim3(CLN / 32, BB), 128>>>(C, W);
    g1_mma<<<dim3(QLN / 128, CLN / 128, BB), 256>>>(Q);
    inv_kernel<<<192, 256>>>();
    g3_mma<<<dim3(QLN / 128, BB), 256>>>(C);
    g2_mma<<<dim3(CLN / 128, BB), 256>>>(Q, C, out);
    g4_mma<<<dim3(CLN / 128, BB), 256>>>(C, out);
}

// round 8
// speedup vs baseline: 3.6924x; 1.1380x over previous
#include <cuda_runtime.h>
#include <cstdint>

#define BB  32
#define DD  128
#define CLN 1024
#define QLN 512

// ---------------- scratch (device globals; no allocations allowed) ----------
__device__ float g_Aeff[BB * CLN * DD];         // wq + wqc*C^T
__device__ float g_bias[BB * CLN];
__device__ float g_S[(size_t)BB * CLN * QLN];   // exp(S)  (B, CL, QL)
__device__ float g_rsum[BB * CLN];              // row sums (raw)
__device__ float g_csum[BB * QLN];              // col sums (raw)
__device__ float g_Tt[BB * DD * QLN];           // (S2^T C)^T  (B, D, QL)

// ---------------- helpers -----------------------------------------------------
__device__ __forceinline__ uint32_t s2u(const void* p) {
    uint32_t a;
    asm("{ .reg .u64 t; cvta.to.shared.u64 t, %1; cvt.u32.u64 %0, t; }" : "=r"(a) : "l"(p));
    return a;
}
#define CPC()  asm volatile("cp.async.commit_group;" ::: "memory")
#define CPW0() asm volatile("cp.async.wait_group 0;" ::: "memory")

// cp.async fill: 128 rows x 16 floats, row stride 20 floats
__device__ __forceinline__ void cfill(uint32_t sb, const float* __restrict__ g,
                                      int ld, int row0, int k0, int t) {
#pragma unroll
    for (int j = 0; j < 2; ++j) {
        int lin = t + (j << 8);
        int r = lin >> 2, q = lin & 3;
        asm volatile("cp.async.cg.shared.global [%0], [%1], 16;"
                     :: "r"(sb + r * 80 + q * 16),
                        "l"(g + (size_t)(row0 + r) * ld + k0 + (q << 2)));
    }
}
// 64-row variant (one float4 per thread)
__device__ __forceinline__ void cfill64(uint32_t sb, const float* __restrict__ g,
                                        int ld, int row0, int k0, int t) {
    int r = t >> 2, q = t & 3;
    asm volatile("cp.async.cg.shared.global [%0], [%1], 16;"
                 :: "r"(sb + r * 80 + q * 16),
                    "l"(g + (size_t)(row0 + r) * ld + k0 + (q << 2)));
}

// transposed fill (LDG part): src [k][n] row-major ld; chunk = 16 k-rows x 128 n
__device__ __forceinline__ void tload(const float* __restrict__ g, int ld,
                                      int n0, int k0, int t, float v[8]) {
    int q = t & 127, cs = (t >> 7) << 3;
#pragma unroll
    for (int i = 0; i < 8; ++i)
        v[i] = g[(size_t)(k0 + cs + i) * ld + n0 + q];
}
__device__ __forceinline__ void tstore(float* smf, int t, const float v[8]) {
    int q = t & 127, cs = (t >> 7) << 3;
#pragma unroll
    for (int i = 0; i < 8; ++i) smf[q * 20 + cs + i] = v[i];
}

// ---------------- mma.sync tf32 ----------------------------------------------
#define MMA_TF32(D, A, B)                                                          \
    asm volatile(                                                                  \
        "mma.sync.aligned.m16n8k8.row.col.f32.tf32.tf32.f32 "                      \
        "{%0,%1,%2,%3}, {%4,%5,%6,%7}, {%8,%9}, {%0,%1,%2,%3};"                    \
        : "+f"((D)[0]), "+f"((D)[1]), "+f"((D)[2]), "+f"((D)[3])                   \
        : "r"((A)[0]), "r"((A)[1]), "r"((A)[2]), "r"((A)[3]),                      \
          "r"((B)[0]), "r"((B)[1]))

__device__ __forceinline__ void mma_chunk(const float* __restrict__ As,
                                          const float* __restrict__ Bs,
                                          float acc[4][4][4],
                                          int wm, int wn, int g, int tg) {
#pragma unroll
    for (int kk = 0; kk < 2; ++kk) {
        int kc = (kk << 3) + tg;
        unsigned a[4][4], bf[4][2];
#pragma unroll
        for (int mi = 0; mi < 4; ++mi) {
            const float* p = As + (wm + (mi << 4) + g) * 20 + kc;
            a[mi][0] = __float_as_uint(p[0]);
            a[mi][1] = __float_as_uint(p[160]);
            a[mi][2] = __float_as_uint(p[4]);
            a[mi][3] = __float_as_uint(p[164]);
        }
#pragma unroll
        for (int ni = 0; ni < 4; ++ni) {
            const float* p = Bs + (wn + (ni << 3) + g) * 20 + kc;
            bf[ni][0] = __float_as_uint(p[0]);
            bf[ni][1] = __float_as_uint(p[4]);
        }
#pragma unroll
        for (int mi = 0; mi < 4; ++mi)
#pragma unroll
            for (int ni = 0; ni < 4; ++ni) MMA_TF32(acc[mi][ni], a[mi], bf[ni]);
    }
}

// fused variant: one A (2 mi), two B operands
__device__ __forceinline__ void mma_chunk2(const float* __restrict__ As,
                                           const float* __restrict__ Bs1,
                                           const float* __restrict__ Bs2,
                                           float ac1[2][4][4], float ac2[2][4][4],
                                           int wm, int wn, int g, int tg) {
#pragma unroll
    for (int kk = 0; kk < 2; ++kk) {
        int kc = (kk << 3) + tg;
        unsigned a[2][4], b1[4][2], b2[4][2];
#pragma unroll
        for (int mi = 0; mi < 2; ++mi) {
            const float* p = As + (wm + (mi << 4) + g) * 20 + kc;
            a[mi][0] = __float_as_uint(p[0]);
            a[mi][1] = __float_as_uint(p[160]);
            a[mi][2] = __float_as_uint(p[4]);
            a[mi][3] = __float_as_uint(p[164]);
        }
#pragma unroll
        for (int ni = 0; ni < 4; ++ni) {
            const float* p = Bs1 + (wn + (ni << 3) + g) * 20 + kc;
            b1[ni][0] = __float_as_uint(p[0]);
            b1[ni][1] = __float_as_uint(p[4]);
            const float* p2 = Bs2 + (wn + (ni << 3) + g) * 20 + kc;
            b2[ni][0] = __float_as_uint(p2[0]);
            b2[ni][1] = __float_as_uint(p2[4]);
        }
#pragma unroll
        for (int mi = 0; mi < 2; ++mi)
#pragma unroll
            for (int ni = 0; ni < 4; ++ni) {
                MMA_TF32(ac1[mi][ni], a[mi], b1[ni]);
                MMA_TF32(ac2[mi][ni], a[mi], b2[ni]);
            }
    }
}

// ---------------- prepC: Aeff/bias + zero the sum buffers ---------------------
// grid (CLN/64, BB), 256 threads; warp-per-c, no inner block syncs
__global__ __launch_bounds__(256) void prepC_kernel(const float* __restrict__ C,
                                                    const float* __restrict__ W) {
    __shared__ float tile[128 * 68];
    int b = blockIdx.y, c0 = blockIdx.x << 6;
    int t = threadIdx.x, warp = t >> 5, lane = t & 31;
    // zero sum buffers (covers BB*CLN=32768 and BB*QLN=16384)
    int gi = (blockIdx.y * 16 + blockIdx.x) * 256 + t;
    if (gi < BB * CLN) g_rsum[gi] = 0.f;
    if (gi < BB * QLN) g_csum[gi] = 0.f;
    // load C tile [128 d][64 c]
#pragma unroll
    for (int i = 0; i < 8; ++i) {
        int idx = t + (i << 8);
        int d = idx >> 4, c4 = idx & 15;
        float4 v = *(const float4*)(C + ((size_t)b * DD + d) * CLN + c0 + (c4 << 2));
        *(float4*)(tile + d * 68 + (c4 << 2)) = v;
    }
    __syncthreads();
#pragma unroll
    for (int k = 0; k < 8; ++k) {
        int cc = (warp << 3) + k;
        size_t rc = (size_t)b * CLN + c0 + cc;
        const float* w = W + rc * (3 * DD);
        int d0 = lane << 2;
        float4 wq = *(const float4*)(w + d0);
        float4 wc = *(const float4*)(w + DD + d0);
        float4 wqc = *(const float4*)(w + 2 * DD + d0);
        float ct0 = tile[(d0 + 0) * 68 + cc];
        float ct1 = tile[(d0 + 1) * 68 + cc];
        float ct2 = tile[(d0 + 2) * 68 + cc];
        float ct3 = tile[(d0 + 3) * 68 + cc];
        float4 ae = make_float4(wq.x + wqc.x * ct0, wq.y + wqc.y * ct1,
                                wq.z + wqc.z * ct2, wq.w + wqc.w * ct3);
        *(float4*)(g_Aeff + (rc << 7) + d0) = ae;
        float v = wc.x * ct0 + wc.y * ct1 + wc.z * ct2 + wc.w * ct3;
#pragma unroll
        for (int o = 16; o; o >>= 1) v += __shfl_xor_sync(0xffffffffu, v, o);
        if (lane == 0) g_bias[rc] = v;
    }
}

// ---------------- G1: expS = exp(Aeff @ Q + bias); row/col sums via atomics ---
__global__ __launch_bounds__(256) void g1_mma(const float* __restrict__ Qin) {
    __shared__ float sm[10240];
    int b = blockIdx.z, n0 = blockIdx.x << 7, m0 = blockIdx.y << 7;
    const float* A = g_Aeff + (size_t)b * CLN * DD;
    const float* Qp = Qin + (size_t)b * DD * QLN;
    uint32_t su = s2u(sm);
    int t = threadIdx.x, lane = t & 31, warp = t >> 5;
    int g = lane >> 2, tg = lane & 3;
    int wm = (warp >> 2) << 6, wn = (warp & 3) << 5;
    float acc[4][4][4] = {};
    const int KT = DD / 16;
    float bv[8];
    cfill(su, A, DD, m0, 0, t);
    tload(Qp, QLN, n0, 0, t, bv);
    tstore(sm + 5120, t, bv);
    CPC();
    for (int i = 0; i < KT; ++i) {
        if (i + 1 < KT) tload(Qp, QLN, n0, (i + 1) * 16, t, bv);
        CPW0();
        __syncthreads();
        if (i + 1 < KT) {
            int s = (i + 1) & 1;
            cfill(su + s * 10240, A, DD, m0, (i + 1) * 16, t);
            tstore(sm + 5120 + s * 2560, t, bv);
            CPC();
        }
        mma_chunk(sm + (i & 1) * 2560, sm + 5120 + (i & 1) * 2560, acc, wm, wn, g, tg);
    }
    const float* bp = g_bias + b * CLN + m0;
#pragma unroll
    for (int mi = 0; mi < 4; ++mi)
#pragma unroll
        for (int h = 0; h < 2; ++h) {
            float bbv = bp[wm + (mi << 4) + g + (h << 3)];
#pragma unroll
            for (int ni = 0; ni < 4; ++ni) {
                acc[mi][ni][2 * h] = __expf(acc[mi][ni][2 * h] + bbv);
                acc[mi][ni][2 * h + 1] = __expf(acc[mi][ni][2 * h + 1] + bbv);
            }
        }
    float* Sp = g_S + (size_t)b * CLN * QLN;
#pragma unroll
    for (int mi = 0; mi < 4; ++mi)
#pragma unroll
        for (int h = 0; h < 2; ++h) {
            int row = m0 + wm + (mi << 4) + g + (h << 3);
#pragma unroll
            for (int ni = 0; ni < 4; ++ni) {
                int col = n0 + wn + (ni << 3) + (tg << 1);
                *(float2*)(Sp + (size_t)row * QLN + col) =
                    make_float2(acc[mi][ni][2 * h], acc[mi][ni][2 * h + 1]);
            }
        }
    {   // row sums (reduce over tg lanes)
        float rs[4][2];
#pragma unroll
        for (int mi = 0; mi < 4; ++mi)
#pragma unroll
            for (int h = 0; h < 2; ++h) {
                float s = 0.f;
#pragma unroll
                for (int ni = 0; ni < 4; ++ni) s += acc[mi][ni][2 * h] + acc[mi][ni][2 * h + 1];
                rs[mi][h] = s;
            }
#pragma unroll
        for (int o = 1; o <= 2; o <<= 1)
#pragma unroll
            for (int mi = 0; mi < 4; ++mi)
#pragma unroll
                for (int h = 0; h < 2; ++h)
                    rs[mi][h] += __shfl_xor_sync(0xffffffffu, rs[mi][h], o);
        if (tg == 0) {
            float* rp = g_rsum + b * CLN + m0;
#pragma unroll
            for (int mi = 0; mi < 4; ++mi)
#pragma unroll
                for (int h = 0; h < 2; ++h)
                    atomicAdd(rp + wm + (mi << 4) + g + (h << 3), rs[mi][h]);
        }
    }
    {   // col sums (reduce over g lanes)
        float cs[4][2];
#pragma unroll
        for (int ni = 0; ni < 4; ++ni)
#pragma unroll
            for (int p = 0; p < 2; ++p) {
                float s = 0.f;
#pragma unroll
                for (int mi = 0; mi < 4; ++mi) s += acc[mi][ni][p] + acc[mi][ni][2 + p];
                cs[ni][p] = s;
            }
#pragma unroll
        for (int o = 4; o <= 16; o <<= 1)
#pragma unroll
            for (int ni = 0; ni < 4; ++ni)
#pragma unroll
                for (int p = 0; p < 2; ++p)
                    cs[ni][p] += __shfl_xor_sync(0xffffffffu, cs[ni][p], o);
        if (g == 0) {
            float* cp = g_csum + b * QLN + n0;
#pragma unroll
            for (int ni = 0; ni < 4; ++ni)
#pragma unroll
                for (int p = 0; p < 2; ++p)
                    atomicAdd(cp + wn + (ni << 3) + (tg << 1) + p, cs[ni][p]);
        }
    }
}

// ---------------- G3: Tt[d][q] = (sum_c C[d][c] expS[c][q]) / csum[q] ---------
__global__ __launch_bounds__(256) void g3_mma(const float* __restrict__ Cin) {
    __shared__ float sm[10240];
    int b = blockIdx.y, n0 = blockIdx.x << 7;
    const float* Ap = Cin + (size_t)b * DD * CLN;
    const float* Ep = g_S + (size_t)b * CLN * QLN;
    uint32_t su = s2u(sm);
    int t = threadIdx.x, lane = t & 31, warp = t >> 5;
    int g = lane >> 2, tg = lane & 3;
    int wm = (warp >> 2) << 6, wn = (warp & 3) << 5;
    float acc[4][4][4] = {};
    const int KT = CLN / 16;
    float bv[8];
    cfill(su, Ap, CLN, 0, 0, t);
    tload(Ep, QLN, n0, 0, t, bv);
    tstore(sm + 5120, t, bv);
    CPC();
    for (int i = 0; i < KT; ++i) {
        if (i + 1 < KT) tload(Ep, QLN, n0, (i + 1) * 16, t, bv);
        CPW0();
        __syncthreads();
        if (i + 1 < KT) {
            int s = (i + 1) & 1;
            cfill(su + s * 10240, Ap, CLN, 0, (i + 1) * 16, t);
            tstore(sm + 5120 + s * 2560, t, bv);
            CPC();
        }
        mma_chunk(sm + (i & 1) * 2560, sm + 5120 + (i & 1) * 2560, acc, wm, wn, g, tg);
    }
    float* Ttp = g_Tt + (size_t)b * DD * QLN;
    const float* ci = g_csum + b * QLN + n0;
    float r0[4], r1[4];
#pragma unroll
    for (int ni = 0; ni < 4; ++ni) {
        int col = wn + (ni << 3) + (tg << 1);
        r0[ni] = 1.f / ci[col];
        r1[ni] = 1.f / ci[col + 1];
    }
#pragma unroll
    for (int mi = 0; mi < 4; ++mi)
#pragma unroll
        for (int h = 0; h < 2; ++h) {
            int d = wm + (mi << 4) + g + (h << 3);
#pragma unroll
            for (int ni = 0; ni < 4; ++ni) {
                int col = wn + (ni << 3) + (tg << 1);
                float2 v = make_float2(acc[mi][ni][2 * h] * r0[ni],
                                       acc[mi][ni][2 * h + 1] * r1[ni]);
                *(float2*)(Ttp + (size_t)d * QLN + n0 + col) = v;
            }
        }
}

// ---------------- G24 fused: all four output blocks ---------------------------
// block tile M=64 (CL), N=128 (D), K=QL=512 ; A=expS shared, B1=Q, B2=Tt
// dynamic smem: A 2x1280 + B1 2x2560 + B2 2x2560 = 12800 floats (51200 B)
__global__ __launch_bounds__(256) void g24_mma(const float* __restrict__ Qin,
                                               const float* __restrict__ Cin,
                                               float* __restrict__ out) {
    extern __shared__ float sm[];
    int b = blockIdx.y, m0 = blockIdx.x << 6;
    const float* A = g_S + (size_t)b * CLN * QLN;
    const float* B1 = Qin + (size_t)b * DD * QLN;
    const float* B2 = g_Tt + (size_t)b * DD * QLN;
    uint32_t su = s2u(sm);
    int t = threadIdx.x, lane = t & 31, warp = t >> 5;
    int g = lane >> 2, tg = lane & 3;
    int wm = (warp >> 2) << 5, wn = (warp & 3) << 5;
    float ac1[2][4][4] = {}, ac2[2][4][4] = {};
    const int KT = QLN / 16;
    cfill64(su, A, QLN, m0, 0, t);
    cfill(su + 10240, B1, QLN, 0, 0, t);
    cfill(su + 30720, B2, QLN, 0, 0, t);
    CPC();
    for (int i = 0; i < KT; ++i) {
        CPW0();
        __syncthreads();
        if (i + 1 < KT) {
            int s = (i + 1) & 1;
            cfill64(su + s * 5120, A, QLN, m0, (i + 1) * 16, t);
            cfill(su + 10240 + s * 10240, B1, QLN, 0, (i + 1) * 16, t);
            cfill(su + 30720 + s * 10240, B2, QLN, 0, (i + 1) * 16, t);
            CPC();
        }
        mma_chunk2(sm + (i & 1) * 1280, sm + 2560 + (i & 1) * 2560,
                   sm + 7680 + (i & 1) * 2560, ac1, ac2, wm, wn, g, tg);
    }
    // epilogue: stage both outputs per 32-row chunk, write 4 output blocks
    const float* rp = g_rsum + b * CLN;
    size_t ob = (size_t)b * (4 * DD) * CLN;
    float* smA = sm;            // 32 x 133
    float* smB = sm + 4256;     // 32 x 133
    for (int ch = 0; ch < 2; ++ch) {
        __syncthreads();
        if ((warp >> 2) == ch) {
#pragma unroll
            for (int mi = 0; mi < 2; ++mi)
#pragma unroll
                for (int h = 0; h < 2; ++h) {
                    int ml = (mi << 4) + g + (h << 3);
                    int row = m0 + wm + (mi << 4) + g + (h << 3);
                    float sc = 1.f / rp[row];
#pragma unroll
                    for (int ni = 0; ni < 4; ++ni) {
                        int n = wn + (ni << 3) + (tg << 1);
                        smA[ml * 133 + n] = ac1[mi][ni][2 * h] * sc;
                        smA[ml * 133 + n + 1] = ac1[mi][ni][2 * h + 1] * sc;
                        smB[ml * 133 + n] = ac2[mi][ni][2 * h] * sc;
                        smB[ml * 133 + n + 1] = ac2[mi][ni][2 * h + 1] * sc;
                    }
                }
        }
        __syncthreads();
        int cl = t & 31, dw = t >> 5;
        int c = m0 + (ch << 5) + cl;
#pragma unroll
        for (int i = 0; i < 16; ++i) {
            int d = dw + (i << 3);
            float v1 = smA[cl * 133 + d];
            float v2 = smB[cl * 133 + d];
            float cv = Cin[((size_t)b * DD + d) * CLN + c];
            out[ob + (size_t)d * CLN + c] = cv;
            out[ob + (size_t)(DD + d) * CLN + c] = v1;
            out[ob + (size_t)(2 * DD + d) * CLN + c] = cv * v1;
            out[ob + (size_t)(3 * DD + d) * CLN + c] = cv * v2;
        }
    }
}

// ---------------- launch ------------------------------------------------------
extern "C" void kernel_launch(void* const* d_in, const int* in_sizes, int n_in,
                              void* d_out, int out_size) {
    const float* C = (const float*)d_in[0];
    const float* Q = (const float*)d_in[1];
    const float* W = (const float*)d_in[2];
    float* out = (float*)d_out;

    const int SM24 = 51200;
    cudaFuncSetAttribute(g24_mma, cudaFuncAttributeMaxDynamicSharedMemorySize, SM24);

    prepC_kernel<<<dim3(CLN / 64, BB), 256>>>(C, W);
    g1_mma<<<dim3(QLN / 128, CLN / 128, BB), 256>>>(Q);
    g3_mma<<<dim3(QLN / 128, BB), 256>>>(C);
    g24_mma<<<dim3(CLN / 64, BB), 256, SM24>>>(Q, C, out);
}